// round 3
// baseline (speedup 1.0000x reference)
#include <cuda_runtime.h>
#include <stdint.h>

#define NEXP 8
#define DIN 1024
#define DHID 4096
#define DOUT 1024
#define NTOK 16384
#define NPAIR 32768
#define MAXT 264

// ---------------- scratch (static device globals; no allocation) ----------
__device__ float g_h[134217728];          // 32768 x 4096 fp32 hidden acts (512MB)
__device__ int   g_pair_tok[NPAIR];
__device__ float g_pair_w[NPAIR];
__device__ int   g_counts[NEXP];
__device__ int   g_cursor[NEXP];
__device__ int   g_offsets[NEXP + 1];
__device__ int   g_tile_e[MAXT];
__device__ int   g_tile_start[MAXT];
__device__ int   g_tile_rows[MAXT];
__device__ int   g_ntiles;
__device__ int   g_top_idx[NTOK * 2];
__device__ float g_top_w[NTOK * 2];

// ---------------- small kernels ----------------
__global__ void zero_kernel() {
  int t = threadIdx.x;
  if (t < NEXP) { g_counts[t] = 0; g_cursor[t] = 0; }
}

__global__ void gate_kernel(const float* __restrict__ x,
                            const float* __restrict__ gw,
                            const float* __restrict__ gb) {
  int warp = threadIdx.x >> 5, lane = threadIdx.x & 31;
  int tok = blockIdx.x * 4 + warp;
  const float* xr = x + (size_t)tok * DIN;
  float acc[NEXP];
#pragma unroll
  for (int e = 0; e < NEXP; e++) acc[e] = 0.f;
  for (int k = lane; k < DIN; k += 32) {
    float xv = xr[k];
    const float* w = gw + k * NEXP;
#pragma unroll
    for (int e = 0; e < NEXP; e++) acc[e] += xv * w[e];
  }
#pragma unroll
  for (int e = 0; e < NEXP; e++) {
#pragma unroll
    for (int off = 16; off > 0; off >>= 1)
      acc[e] += __shfl_down_sync(0xffffffffu, acc[e], off);
  }
  if (lane == 0) {
    float v[NEXP];
#pragma unroll
    for (int e = 0; e < NEXP; e++) v[e] = acc[e] + gb[e];
    int i0 = 0;
#pragma unroll
    for (int e = 1; e < NEXP; e++) if (v[e] > v[i0]) i0 = e;
    int i1 = (i0 == 0) ? 1 : 0;
#pragma unroll
    for (int e = 0; e < NEXP; e++)
      if (e != i0 && v[e] > v[i1]) i1 = e;
    float ee = expf(v[i1] - v[i0]);
    float w0 = 1.f / (1.f + ee);
    float w1 = ee * w0;
    g_top_idx[tok * 2]     = i0;
    g_top_idx[tok * 2 + 1] = i1;
    g_top_w[tok * 2]       = w0;
    g_top_w[tok * 2 + 1]   = w1;
    atomicAdd(&g_counts[i0], 1);
    atomicAdd(&g_counts[i1], 1);
  }
}

__global__ void scan_kernel() {
  int off = 0, nt = 0;
  for (int e = 0; e < NEXP; e++) {
    g_offsets[e] = off;
    int m = g_counts[e];
    for (int r = 0; r < m; r += 128) {
      g_tile_e[nt]     = e;
      g_tile_start[nt] = off + r;
      g_tile_rows[nt]  = (m - r < 128) ? (m - r) : 128;
      nt++;
    }
    off += m;
  }
  g_offsets[NEXP] = off;
  g_ntiles = nt;
}

__global__ void scatter_kernel() {
  int tok = blockIdx.x * blockDim.x + threadIdx.x;
  if (tok >= NTOK) return;
#pragma unroll
  for (int s = 0; s < 2; s++) {
    int e = g_top_idx[tok * 2 + s];
    int pos = g_offsets[e] + atomicAdd(&g_cursor[e], 1);
    g_pair_tok[pos] = tok;
    g_pair_w[pos]   = g_top_w[tok * 2 + s];
  }
}

// ---------------- GEMM core (tf32 mma.sync, cp.async double buffer) -------
__device__ __forceinline__ uint32_t f2tf(float f) {
  uint32_t u;
  asm("cvt.rna.tf32.f32 %0, %1;" : "=r"(u) : "f"(f));
  return u;
}

#define MMA_TF32(d, a, b)                                                    \
  asm volatile(                                                              \
      "mma.sync.aligned.m16n8k8.row.col.f32.tf32.tf32.f32 "                  \
      "{%0,%1,%2,%3},{%4,%5,%6,%7},{%8,%9},{%0,%1,%2,%3};"                   \
      : "+f"(d[0]), "+f"(d[1]), "+f"(d[2]), "+f"(d[3])                       \
      : "r"(a[0]), "r"(a[1]), "r"(a[2]), "r"(a[3]), "r"(b[0]), "r"(b[1]))

__device__ __forceinline__ void cpa16(uint32_t dst, const void* src, int sbytes) {
  asm volatile("cp.async.cg.shared.global [%0], [%1], 16, %2;\n" ::"r"(dst),
               "l"(src), "r"(sbytes));
}

// MODE 0: A = gathered x rows, out = relu(A@w1+b1) -> g_h
// MODE 1: A = g_h rows,        out = atomicAdd(out[tok], w * (A@w2+b2))
template <int MODE>
__global__ __launch_bounds__(256, 2) void moe_gemm(const float* __restrict__ X,
                                                   const float* __restrict__ W,
                                                   const float* __restrict__ Bias,
                                                   float* __restrict__ Out) {
  constexpr int KDIM = (MODE == 0) ? DIN : DHID;
  constexpr int NDIM = (MODE == 0) ? DHID : DOUT;
  constexpr int BM = 128, BN = 128, BK = 32;
  constexpr int AST = 36;   // A smem row stride (floats): conflict-free frags
  constexpr int BST = 136;  // B smem row stride (floats): conflict-free frags
  constexpr int KT = KDIM / BK;
  extern __shared__ float sm[];
  float* As = sm;                  // [2][BM][AST]
  float* Bs = sm + 2 * BM * AST;   // [2][BK][BST]

  int tile = blockIdx.y;
  if (tile >= g_ntiles) return;
  int e      = g_tile_e[tile];
  int pstart = g_tile_start[tile];
  int rows   = g_tile_rows[tile];
  int n0 = blockIdx.x * BN;
  const float* Wb = W + (size_t)e * KDIM * NDIM;

  int tid  = threadIdx.x;
  int lane = tid & 31, warp = tid >> 5;
  int g = lane >> 2, t = lane & 3;
  int wm = warp >> 2, wn = warp & 3;  // 2 x 4 warp grid

  // A tile loads: 2 threads per row, 16 floats (4 x cp.async16) each
  int arow  = tid >> 1;
  int ahalf = (tid & 1) * 16;
  bool avalid = arow < rows;
  const float* arow_ptr;
  if (MODE == 0) {
    int tok = avalid ? g_pair_tok[pstart + arow] : 0;
    arow_ptr = X + (size_t)tok * DIN;
  } else {
    arow_ptr = g_h + (size_t)(pstart + (avalid ? arow : 0)) * DHID;
  }
  int abytes = avalid ? 16 : 0;  // zero-fill invalid rows

  // B tile loads: 8 threads per row, 16 floats each
  int brow = tid >> 3;
  int bcol = (tid & 7) * 16;
  const float* brow_ptr = Wb + (size_t)brow * NDIM + n0 + bcol;

  float acc[4][4][4];
#pragma unroll
  for (int i = 0; i < 4; i++)
#pragma unroll
    for (int j = 0; j < 4; j++)
#pragma unroll
      for (int q = 0; q < 4; q++) acc[i][j][q] = 0.f;

  uint32_t as_base = (uint32_t)__cvta_generic_to_shared(As);
  uint32_t bs_base = (uint32_t)__cvta_generic_to_shared(Bs);
  uint32_t adst = as_base + (uint32_t)(arow * AST + ahalf) * 4;
  uint32_t bdst = bs_base + (uint32_t)(brow * BST + bcol) * 4;
  constexpr uint32_t ABUF = BM * AST * 4;
  constexpr uint32_t BBUF = BK * BST * 4;

  auto issue = [&](int kt, int buf) {
    const float* ap = arow_ptr + kt * BK + ahalf;
    uint32_t ad = adst + buf * ABUF;
#pragma unroll
    for (int i = 0; i < 4; i++) cpa16(ad + i * 16, ap + i * 4, abytes);
    const float* bp = brow_ptr + (size_t)kt * BK * NDIM;
    uint32_t bd = bdst + buf * BBUF;
#pragma unroll
    for (int i = 0; i < 4; i++) cpa16(bd + i * 16, bp + i * 4, 16);
  };

  issue(0, 0);
  asm volatile("cp.async.commit_group;\n");
  int buf = 0;
  for (int kt = 0; kt < KT; kt++) {
    if (kt + 1 < KT) {
      issue(kt + 1, buf ^ 1);
      asm volatile("cp.async.commit_group;\n");
      asm volatile("cp.async.wait_group 1;\n");
    } else {
      asm volatile("cp.async.wait_group 0;\n");
    }
    __syncthreads();
    const float* Ab = As + buf * (BM * AST);
    const float* Bb = Bs + buf * (BK * BST);
#pragma unroll
    for (int ks = 0; ks < 4; ks++) {
      int k0 = ks * 8;
      uint32_t af[4][4], bf[4][2];
#pragma unroll
      for (int mi = 0; mi < 4; mi++) {
        const float* ap = Ab + (wm * 64 + mi * 16 + g) * AST + k0 + t;
        af[mi][0] = f2tf(ap[0]);
        af[mi][1] = f2tf(ap[8 * AST]);
        af[mi][2] = f2tf(ap[4]);
        af[mi][3] = f2tf(ap[8 * AST + 4]);
      }
#pragma unroll
      for (int ni = 0; ni < 4; ni++) {
        const float* bp = Bb + (k0 + t) * BST + wn * 32 + ni * 8 + g;
        bf[ni][0] = f2tf(bp[0]);
        bf[ni][1] = f2tf(bp[4 * BST]);
      }
#pragma unroll
      for (int mi = 0; mi < 4; mi++)
#pragma unroll
        for (int ni = 0; ni < 4; ni++) MMA_TF32(acc[mi][ni], af[mi], bf[ni]);
    }
    __syncthreads();
    buf ^= 1;
  }

  // epilogue
#pragma unroll
  for (int mi = 0; mi < 4; mi++) {
#pragma unroll
    for (int j2 = 0; j2 < 2; j2++) {
      int r = wm * 64 + mi * 16 + g + j2 * 8;
      if (r >= rows) continue;
      int p = pstart + r;
      int tok = 0;
      float wgt = 0.f;
      if (MODE == 1) {
        tok = g_pair_tok[p];
        wgt = g_pair_w[p];
      }
#pragma unroll
      for (int ni = 0; ni < 4; ni++) {
#pragma unroll
        for (int c2 = 0; c2 < 2; c2++) {
          int c = wn * 32 + ni * 8 + t * 2 + c2;
          float v = acc[mi][ni][j2 * 2 + c2] + Bias[(size_t)e * NDIM + n0 + c];
          if (MODE == 0) {
            g_h[(size_t)p * DHID + n0 + c] = fmaxf(v, 0.f);
          } else {
            atomicAdd(&Out[(size_t)tok * DOUT + n0 + c], wgt * v);
          }
        }
      }
    }
  }
}

// ---------------- launch ----------------
extern "C" void kernel_launch(void* const* d_in, const int* in_sizes, int n_in,
                              void* d_out, int out_size) {
  const float* x  = (const float*)d_in[0];
  const float* gw = (const float*)d_in[1];
  const float* gb = (const float*)d_in[2];
  const float* w1 = (const float*)d_in[3];
  const float* b1 = (const float*)d_in[4];
  const float* w2 = (const float*)d_in[5];
  const float* b2 = (const float*)d_in[6];
  float* out = (float*)d_out;

  cudaMemsetAsync(out, 0, (size_t)NTOK * DOUT * sizeof(float));
  zero_kernel<<<1, 32>>>();
  gate_kernel<<<NTOK / 4, 128>>>(x, gw, gb);
  scan_kernel<<<1, 1>>>();
  scatter_kernel<<<NTOK / 256, 256>>>();

  const int smem = (2 * 128 * 36 + 2 * 32 * 136) * 4;  // 71680 B
  cudaFuncSetAttribute(moe_gemm<0>, cudaFuncAttributeMaxDynamicSharedMemorySize, smem);
  cudaFuncSetAttribute(moe_gemm<1>, cudaFuncAttributeMaxDynamicSharedMemorySize, smem);
  moe_gemm<0><<<dim3(DHID / 128, MAXT), 256, smem>>>(x, w1, b1, nullptr);
  moe_gemm<1><<<dim3(DOUT / 128, MAXT), 256, smem>>>(nullptr, w2, b2, out);
}

// round 7
// speedup vs baseline: 2.3404x; 2.3404x over previous
#include <cuda_runtime.h>
#include <cuda_fp16.h>
#include <stdint.h>

#define NEXP 8
#define DIN 1024
#define DHID 4096
#define DOUT 1024
#define NTOK 16384
#define NPAIR 32768
#define MAXT 264

// ---------------- scratch (static device globals; no allocation) ----------
__device__ __half g_hh[134217728];             // 32768 x 4096 fp16 hidden (256MB)
__device__ __half g_xh[NTOK * DIN];            // fp16 x (32MB)
__device__ __half g_w1h[NEXP * DIN * DHID];    // w1^T [e][N=4096][K=1024] (64MB)
__device__ __half g_w2h[NEXP * DHID * DOUT];   // w2^T [e][N=1024][K=4096] (64MB)
__device__ int   g_pair_tok[NPAIR];
__device__ float g_pair_w[NPAIR];
__device__ int   g_counts[NEXP];
__device__ int   g_cursor[NEXP];
__device__ int   g_offsets[NEXP + 1];
__device__ int   g_tile_e[MAXT];
__device__ int   g_tile_start[MAXT];
__device__ int   g_tile_rows[MAXT];
__device__ int   g_ntiles;
__device__ int   g_top_idx[NTOK * 2];
__device__ float g_top_w[NTOK * 2];

// ---------------- small kernels ----------------
__global__ void zero_kernel() {
  int t = threadIdx.x;
  if (t < NEXP) { g_counts[t] = 0; g_cursor[t] = 0; }
}

__global__ void gate_kernel(const float* __restrict__ x,
                            const float* __restrict__ gw,
                            const float* __restrict__ gb) {
  int warp = threadIdx.x >> 5, lane = threadIdx.x & 31;
  int tok = blockIdx.x * 4 + warp;
  const float* xr = x + (size_t)tok * DIN;
  float acc[NEXP];
#pragma unroll
  for (int e = 0; e < NEXP; e++) acc[e] = 0.f;
  for (int k = lane; k < DIN; k += 32) {
    float xv = xr[k];
    const float* w = gw + k * NEXP;
#pragma unroll
    for (int e = 0; e < NEXP; e++) acc[e] += xv * w[e];
  }
#pragma unroll
  for (int e = 0; e < NEXP; e++) {
#pragma unroll
    for (int off = 16; off > 0; off >>= 1)
      acc[e] += __shfl_down_sync(0xffffffffu, acc[e], off);
  }
  if (lane == 0) {
    float v[NEXP];
#pragma unroll
    for (int e = 0; e < NEXP; e++) v[e] = acc[e] + gb[e];
    int i0 = 0;
#pragma unroll
    for (int e = 1; e < NEXP; e++) if (v[e] > v[i0]) i0 = e;
    int i1 = (i0 == 0) ? 1 : 0;
#pragma unroll
    for (int e = 0; e < NEXP; e++)
      if (e != i0 && v[e] > v[i1]) i1 = e;
    float ee = expf(v[i1] - v[i0]);
    float w0 = 1.f / (1.f + ee);
    float w1 = ee * w0;
    g_top_idx[tok * 2]     = i0;
    g_top_idx[tok * 2 + 1] = i1;
    g_top_w[tok * 2]       = w0;
    g_top_w[tok * 2 + 1]   = w1;
    atomicAdd(&g_counts[i0], 1);
    atomicAdd(&g_counts[i1], 1);
  }
}

__global__ void scan_kernel() {
  int off = 0, nt = 0;
  for (int e = 0; e < NEXP; e++) {
    g_offsets[e] = off;
    int m = g_counts[e];
    for (int r = 0; r < m; r += 128) {
      g_tile_e[nt]     = e;
      g_tile_start[nt] = off + r;
      g_tile_rows[nt]  = (m - r < 128) ? (m - r) : 128;
      nt++;
    }
    off += m;
  }
  g_offsets[NEXP] = off;
  g_ntiles = nt;
}

__global__ void scatter_kernel() {
  int tok = blockIdx.x * blockDim.x + threadIdx.x;
  if (tok >= NTOK) return;
#pragma unroll
  for (int s = 0; s < 2; s++) {
    int e = g_top_idx[tok * 2 + s];
    int pos = g_offsets[e] + atomicAdd(&g_cursor[e], 1);
    g_pair_tok[pos] = tok;
    g_pair_w[pos]   = g_top_w[tok * 2 + s];
  }
}

// ---------------- fused prep: zero out + x->fp16 + w1/w2 transpose->fp16 --
#define NB_OUT 16384
#define NB_X   8192
#define NB_W1  32768
#define NB_W2  32768

__device__ __forceinline__ void trt32(const float* S, __half* D, int R, int C,
                                      int r0, int c0, int tid) {
  __shared__ __half t[32][33];
  int tx = tid & 31, ty = tid >> 5;
#pragma unroll
  for (int i = 0; i < 4; i++)
    t[ty + 8 * i][tx] = __float2half_rn(S[(size_t)(r0 + ty + 8 * i) * C + c0 + tx]);
  __syncthreads();
#pragma unroll
  for (int i = 0; i < 4; i++)
    D[(size_t)(c0 + ty + 8 * i) * R + r0 + tx] = t[tx][ty + 8 * i];
}

__global__ void prep_kernel(float* __restrict__ out, const float* __restrict__ x,
                            const float* __restrict__ w1, const float* __restrict__ w2) {
  int b = blockIdx.x, tid = threadIdx.x;
  if (b < NB_OUT) {
    ((float4*)out)[(size_t)b * 256 + tid] = make_float4(0.f, 0.f, 0.f, 0.f);
  } else if (b < NB_OUT + NB_X) {
    size_t i = (size_t)(b - NB_OUT) * 256 + tid;
    float4 v0 = ((const float4*)x)[2 * i];
    float4 v1 = ((const float4*)x)[2 * i + 1];
    __half2 h[4];
    h[0] = __floats2half2_rn(v0.x, v0.y);
    h[1] = __floats2half2_rn(v0.z, v0.w);
    h[2] = __floats2half2_rn(v1.x, v1.y);
    h[3] = __floats2half2_rn(v1.z, v1.w);
    ((uint4*)g_xh)[i] = *(uint4*)h;
  } else if (b < NB_OUT + NB_X + NB_W1) {
    int r = b - NB_OUT - NB_X;
    int e = r >> 12, rem = r & 4095;           // 128*32 = 4096 tiles/expert
    int cx = rem & 127, cy = rem >> 7;         // C/32=128, R/32=32
    trt32(w1 + (size_t)e * DIN * DHID, g_w1h + (size_t)e * DIN * DHID,
          DIN, DHID, cy * 32, cx * 32, tid);
  } else {
    int r = b - NB_OUT - NB_X - NB_W1;
    int e = r >> 12, rem = r & 4095;           // 32*128
    int cx = rem & 31, cy = rem >> 5;          // C/32=32, R/32=128
    trt32(w2 + (size_t)e * DHID * DOUT, g_w2h + (size_t)e * DHID * DOUT,
          DHID, DOUT, cy * 32, cx * 32, tid);
  }
}

// ---------------- fp16 mma.sync GEMM (cp.async 4-stage) ----------------
#define MMA_F16(d, a, b)                                                     \
  asm volatile(                                                              \
      "mma.sync.aligned.m16n8k16.row.col.f32.f16.f16.f32 "                   \
      "{%0,%1,%2,%3},{%4,%5,%6,%7},{%8,%9},{%0,%1,%2,%3};"                   \
      : "+f"(d[0]), "+f"(d[1]), "+f"(d[2]), "+f"(d[3])                       \
      : "r"(a[0]), "r"(a[1]), "r"(a[2]), "r"(a[3]), "r"(b[0]), "r"(b[1]))

// MODE 0: A = gathered g_xh rows, h = relu(A@w1^T+b1) -> g_hh (fp16)
// MODE 1: A = g_hh rows,          out += gatew * (A@w2^T+b2)
template <int MODE>
__global__ __launch_bounds__(256, 2) void moe_mma(const float* __restrict__ Bias,
                                                  float* __restrict__ Out) {
  constexpr int KDIM = (MODE == 0) ? DIN : DHID;
  constexpr int NDIM = (MODE == 0) ? DHID : DOUT;
  constexpr int BK = 32, S = 4;
  constexpr int KT = KDIM / BK;
  constexpr int AST = 40;             // halfs per smem row (20 banks -> cf)
  constexpr int STAGE_H = 2 * 128 * AST;  // A tile + B tile, in halfs
  extern __shared__ __half smh[];

  int tile = blockIdx.y;
  if (tile >= g_ntiles) return;
  int e = g_tile_e[tile], pstart = g_tile_start[tile], rows = g_tile_rows[tile];
  int n0 = blockIdx.x * 128;
  int tid = threadIdx.x;
  int lane = tid & 31, warp = tid >> 5;
  int g = lane >> 2, t = lane & 3;
  int wm = warp >> 2, wn = warp & 3;  // 2 x 4 warps, warp tile 64x32

  const __half* Bsrc = ((MODE == 0) ? g_w1h : g_w2h) + (size_t)e * KDIM * NDIM;

  // loads: each thread owns row (tid>>1) of A and of B, half (tid&1)
  int lrow = tid >> 1;
  int off16 = (tid & 1) * 16;
  bool av = lrow < rows;
  const __half* aptr;
  if (MODE == 0) {
    int tok = av ? g_pair_tok[pstart + lrow] : 0;
    aptr = g_xh + (size_t)tok * DIN + off16;
  } else {
    aptr = g_hh + (size_t)(pstart + (av ? lrow : 0)) * DHID + off16;
  }
  int abytes = av ? 16 : 0;
  const __half* bptr = Bsrc + (size_t)(n0 + lrow) * KDIM + off16;

  uint32_t sb;
  asm("{ .reg .u64 t; cvta.to.shared.u64 t, %1; cvt.u32.u64 %0, t; }"
      : "=r"(sb) : "l"(smh));
  uint32_t adst = sb + (uint32_t)(lrow * AST + off16) * 2;
  uint32_t bdst = adst + 128 * AST * 2;

  auto issue = [&](int c, int s) {
    uint32_t o = (uint32_t)s * (STAGE_H * 2);
    asm volatile("cp.async.cg.shared.global [%0], [%1], 16, %2;"
                 ::"r"(adst + o), "l"(aptr + c * 32), "r"(abytes));
    asm volatile("cp.async.cg.shared.global [%0], [%1], 16, %2;"
                 ::"r"(adst + o + 16), "l"(aptr + c * 32 + 8), "r"(abytes));
    asm volatile("cp.async.cg.shared.global [%0], [%1], 16;"
                 ::"r"(bdst + o), "l"(bptr + c * 32));
    asm volatile("cp.async.cg.shared.global [%0], [%1], 16;"
                 ::"r"(bdst + o + 16), "l"(bptr + c * 32 + 8));
  };

  float acc[4][4][4];
#pragma unroll
  for (int i = 0; i < 4; i++)
#pragma unroll
    for (int j = 0; j < 4; j++)
#pragma unroll
      for (int q = 0; q < 4; q++) acc[i][j][q] = 0.f;

#pragma unroll
  for (int c = 0; c < S - 1; c++) {
    issue(c, c);
    asm volatile("cp.async.commit_group;");
  }

#pragma unroll 1
  for (int k = 0; k < KT; k++) {
    asm volatile("cp.async.wait_group %0;" ::"n"(S - 2));
    __syncthreads();
    const __half* Ab = smh + (k % S) * STAGE_H;
    const __half* Bb = Ab + 128 * AST;
#pragma unroll
    for (int ks = 0; ks < 2; ks++) {
      int k0 = ks * 16;
      uint32_t af[4][4], bf[4][2];
#pragma unroll
      for (int mi = 0; mi < 4; mi++) {
        const __half* ap = Ab + (wm * 64 + mi * 16 + g) * AST + k0 + 2 * t;
        af[mi][0] = *(const uint32_t*)ap;
        af[mi][1] = *(const uint32_t*)(ap + 8 * AST);
        af[mi][2] = *(const uint32_t*)(ap + 8);
        af[mi][3] = *(const uint32_t*)(ap + 8 * AST + 8);
      }
#pragma unroll
      for (int ni = 0; ni < 4; ni++) {
        const __half* bp = Bb + (wn * 32 + ni * 8 + g) * AST + k0 + 2 * t;
        bf[ni][0] = *(const uint32_t*)bp;
        bf[ni][1] = *(const uint32_t*)(bp + 8);
      }
#pragma unroll
      for (int mi = 0; mi < 4; mi++)
#pragma unroll
        for (int ni = 0; ni < 4; ni++) MMA_F16(acc[mi][ni], af[mi], bf[ni]);
    }
    int lc = k + S - 1;
    if (lc < KT) issue(lc, lc % S);
    asm volatile("cp.async.commit_group;");
  }

  // ---------------- epilogue ----------------
#pragma unroll
  for (int mi = 0; mi < 4; mi++) {
#pragma unroll
    for (int j2 = 0; j2 < 2; j2++) {
      int r = wm * 64 + mi * 16 + g + j2 * 8;
      if (r >= rows) continue;
      int p = pstart + r;
      int tok = 0;
      float wgt = 0.f;
      if (MODE == 1) { tok = g_pair_tok[p]; wgt = g_pair_w[p]; }
#pragma unroll
      for (int ni = 0; ni < 4; ni++) {
        int c = wn * 32 + ni * 8 + t * 2;
        const float* bp = Bias + (size_t)e * NDIM + n0 + c;
        float v0 = acc[mi][ni][j2 * 2]     + bp[0];
        float v1 = acc[mi][ni][j2 * 2 + 1] + bp[1];
        if (MODE == 0) {
          __half2 hv = __floats2half2_rn(fmaxf(v0, 0.f), fmaxf(v1, 0.f));
          *(__half2*)(g_hh + (size_t)p * DHID + n0 + c) = hv;
        } else {
          float* op = Out + (size_t)tok * DOUT + n0 + c;
          atomicAdd(op, wgt * v0);
          atomicAdd(op + 1, wgt * v1);
        }
      }
    }
  }
}

// ---------------- launch ----------------
extern "C" void kernel_launch(void* const* d_in, const int* in_sizes, int n_in,
                              void* d_out, int out_size) {
  const float* x  = (const float*)d_in[0];
  const float* gw = (const float*)d_in[1];
  const float* gb = (const float*)d_in[2];
  const float* w1 = (const float*)d_in[3];
  const float* b1 = (const float*)d_in[4];
  const float* w2 = (const float*)d_in[5];
  const float* b2 = (const float*)d_in[6];
  float* out = (float*)d_out;

  zero_kernel<<<1, 32>>>();                                   // launch 0
  gate_kernel<<<NTOK / 4, 128>>>(x, gw, gb);                  // launch 1
  scan_kernel<<<1, 1>>>();                                    // launch 2
  scatter_kernel<<<NTOK / 256, 256>>>();                      // launch 3
  prep_kernel<<<NB_OUT + NB_X + NB_W1 + NB_W2, 256>>>(out, x, w1, w2);  // 4

  const int smem = 4 * 2 * 128 * 40 * 2;  // 81920 B
  cudaFuncSetAttribute(moe_mma<0>, cudaFuncAttributeMaxDynamicSharedMemorySize, smem);
  cudaFuncSetAttribute(moe_mma<1>, cudaFuncAttributeMaxDynamicSharedMemorySize, smem);
  moe_mma<0><<<dim3(DHID / 128, MAXT), 256, smem>>>(b1, nullptr);  // launch 5
  moe_mma<1><<<dim3(DOUT / 128, MAXT), 256, smem>>>(b2, out);      // launch 6
}